// round 17
// baseline (speedup 1.0000x reference)
#include <cuda_runtime.h>
#include <cstdint>

// Z gate (DIM=2, S=1) on wires {0,5,11} of a 24-qubit register.
//   out[n] = (-1)^popc(n & SIGN_MASK) * x_real[n]   (N float32)
// SIGN_MASK bits 23,18,12 -> sign uniform over each 2048-float tile
// (tile offsets span bits 0..10 only).
//
// PERSISTENT (1184 CTAs = 148 SMs x 8) + DEPTH-2 SOFTWARE PIPELINE on
// 2048-float tiles (one 256-bit chunk/thread/tile). Ring of 3 buffers:
// loads run two tiles ahead of stores, so the DRAM read stream never drains
// behind the write stream across ~6.9 iterations/CTA. ~38 regs, same
// occupancy as the depth-1 4096-tile variant (R16, bench 18.50us).

#define SIGN_MASK ((1u << 23) | (1u << 18) | (1u << 12))
#define THREADS   256u
#define N_TILES   8192u           // (1<<24) / 2048
#define GRID      1184u           // 148 SMs * 8 resident CTAs

struct f8 { float v[8]; };

__device__ __forceinline__ f8 ldg256(const float* p) {
    f8 r;
    asm("ld.global.nc.v8.b32 {%0,%1,%2,%3,%4,%5,%6,%7}, [%8];"
        : "=f"(r.v[0]), "=f"(r.v[1]), "=f"(r.v[2]), "=f"(r.v[3]),
          "=f"(r.v[4]), "=f"(r.v[5]), "=f"(r.v[6]), "=f"(r.v[7])
        : "l"(p));
    return r;
}

__device__ __forceinline__ void stg256_ef(float* p, const f8& r) {
    asm volatile("st.global.L2::evict_first.v8.b32 [%0], {%1,%2,%3,%4,%5,%6,%7,%8};"
                 :: "l"(p),
                    "f"(r.v[0]), "f"(r.v[1]), "f"(r.v[2]), "f"(r.v[3]),
                    "f"(r.v[4]), "f"(r.v[5]), "f"(r.v[6]), "f"(r.v[7])
                 : "memory");
}

__device__ __forceinline__ float tile_sign(unsigned tile) {
    // tile base = tile << 11; only bits >= 12 carry sign.
    return (__popc((tile << 11) & SIGN_MASK) & 1) ? -1.0f : 1.0f;
}

__device__ __forceinline__ void emit(float* out, unsigned tile, unsigned o, f8 x) {
    float s = tile_sign(tile);
    #pragma unroll
    for (int k = 0; k < 8; k++) x.v[k] *= s;
    stg256_ef(out + (tile << 11) + o, x);
}

__global__ void __launch_bounds__(256) z_phase_kernel(
    const float* __restrict__ xr,
    float* __restrict__ out)
{
    unsigned o = threadIdx.x << 3;        // this thread's 32B chunk in a tile

    // N_TILES / GRID = 6..7 iterations; GRID*2 < N_TILES so both prologue
    // loads are always valid.
    unsigned t0 = blockIdx.x;
    unsigned t1 = t0 + GRID;

    f8 b0 = ldg256(xr + (t0 << 11) + o);
    f8 b1 = ldg256(xr + (t1 << 11) + o);

    unsigned next = t1 + GRID;
    while (next < N_TILES) {
        f8 b2 = ldg256(xr + (next << 11) + o);   // run 2 tiles ahead
        emit(out, t0, o, b0);
        t0 = t1; b0 = b1;
        t1 = next; b1 = b2;
        next += GRID;
    }

    // Drain the two in-flight tiles.
    emit(out, t0, o, b0);
    emit(out, t1, o, b1);
}

extern "C" void kernel_launch(void* const* d_in, const int* in_sizes, int n_in,
                              void* d_out, int out_size)
{
    const float* xr = (const float*)d_in[0];
    float* out = (float*)d_out;

    z_phase_kernel<<<GRID, THREADS>>>(xr, out);
}